// round 16
// baseline (speedup 1.0000x reference)
#include <cuda_runtime.h>
#include <math.h>

// Problem constants
#define NB 128
#define NI 1152
#define NO 32
#define ND 16
#define KSUB 922          // ceil(0.8 * 1152)
#define CHUNKS 9
#define IPB (NI / CHUNKS) // 128 i's per block (pass1)
#define IPW (IPB / 8)     // 16 i's per warp
#define MAXREJ 232        // >= NI - KSUB = 230
#define OH 16             // o's per fused block (half of NO)
#define ROWK 1153         // key row stride in words (odd -> conflict-light)
#define ROWH 257          // hist row stride in words

// Scratch (no allocation allowed -> __device__ globals). Per-chunk partials:
// written race-free by pass1 (no atomics, no zeroing kernel needed).
__device__ float g_part [NB * CHUNKS * NO * ND];
__device__ float g_partd[NB * CHUNKS * NO];

// ---------------------------------------------------------------------------
// Pass 1: per-chunk partial sums of u*n and n  (no atomics, no pre-zero)
// ---------------------------------------------------------------------------
__global__ void __launch_bounds__(256) k_pass1(const float* __restrict__ u) {
    int b = blockIdx.x / CHUNKS;
    int chunk = blockIdx.x % CHUNKS;
    int w = threadIdx.x >> 5;
    int lane = threadIdx.x & 31;

    const float4* up = (const float4*)u + (size_t)b * NI * (NO * ND / 4);
    float acc[ND];
    float accden = 0.f;
#pragma unroll
    for (int d = 0; d < ND; d++) acc[d] = 0.f;

    int i0 = chunk * IPB + w * IPW;
#pragma unroll 2
    for (int ii = 0; ii < IPW; ii++) {
        const float4* row = up + (size_t)(i0 + ii) * (NO * ND / 4) + lane * (ND / 4);
        float4 a0 = row[0], a1 = row[1], a2 = row[2], a3 = row[3];
        float va[16] = {a0.x, a0.y, a0.z, a0.w, a1.x, a1.y, a1.z, a1.w,
                        a2.x, a2.y, a2.z, a2.w, a3.x, a3.y, a3.z, a3.w};
        float s = 0.f;
#pragma unroll
        for (int d = 0; d < 16; d++) s += va[d] * va[d];
        float n = sqrtf(s);
#pragma unroll
        for (int d = 0; d < 16; d++) acc[d] += va[d] * n;
        accden += n;
    }

    __shared__ float snum[8][NO * ND];
    __shared__ float sden[8][NO];
#pragma unroll
    for (int d = 0; d < ND; d++) snum[w][d * NO + lane] = acc[d];
    sden[w][lane] = accden;
    __syncthreads();

    float* gp = &g_part[(size_t)(b * CHUNKS + chunk) * NO * ND];
    for (int idx = threadIdx.x; idx < NO * ND; idx += 256) {
        int d = idx / NO, o = idx % NO;
        float s = 0.f;
#pragma unroll
        for (int ww = 0; ww < 8; ww++) s += snum[ww][idx];
        gp[o * ND + d] = s;
    }
    if (threadIdx.x < NO) {
        float s = 0.f;
#pragma unroll
        for (int ww = 0; ww < 8; ww++) s += sden[ww][threadIdx.x];
        g_partd[(b * CHUNKS + chunk) * NO + threadIdx.x] = s;
    }
}

__device__ __forceinline__ unsigned mono_key(float f) {
    unsigned x = __float_as_uint(f);
    return (x & 0x80000000u) ? ~x : (x | 0x80000000u);
}

// Warp pick: 256-bin hist row -> bucket containing rank k; updates k.
__device__ __forceinline__ unsigned warp_pick(const int* oh, int lane, int& k) {
    int h[8], seg = 0;
#pragma unroll
    for (int t = 0; t < 8; t++) { h[t] = oh[lane * 8 + t]; seg += h[t]; }
    int incl = seg;
#pragma unroll
    for (int off = 1; off < 32; off <<= 1) {
        int n_ = __shfl_up_sync(0xffffffffu, incl, off);
        if (lane >= off) incl += n_;
    }
    int excl = incl - seg;
    bool has = (excl < k) && (excl + seg >= k);
    unsigned mba = __ballot_sync(0xffffffffu, has);
    int src = __ffs(mba) - 1;
    int bsel = 0, kk2 = 0;
    if (lane == src) {
        int run = excl;
#pragma unroll
        for (int t = 0; t < 8; t++) {
            if (run + h[t] >= k) { bsel = lane * 8 + t; kk2 = k - run; break; }
            run += h[t];
        }
    }
    bsel = __shfl_sync(0xffffffffu, bsel, src);
    k = __shfl_sync(0xffffffffu, kk2, src);
    return (unsigned)bsel;
}

// ---------------------------------------------------------------------------
// Fused pass2 + select + fixup: one 512-thread block per (b, o-half).
// grid = 256 -> 2 blocks/SM (tails overlap), one wave. Streams only its
// 16-o half of u[b]; keys in smem; warp w selects+gathers for o = obase+w.
// ---------------------------------------------------------------------------
__global__ void __launch_bounds__(512) k_pass2sel(const float* __restrict__ u,
                                                  float* __restrict__ out) {
    extern __shared__ char smem[];
    float*    sv    = (float*)smem;                    // OH*ND    = 1024 B [d*OH+ol]
    float*    snum  = sv + OH * ND;                    // OH*ND    = 1024 B [ol*ND+d]
    float*    sden  = snum + OH * ND;                  // OH       =   64 B
    unsigned* keys  = (unsigned*)(sden + OH);          // OH*ROWK*4 = 73792 B
    int*      hist  = (int*)(keys + OH * ROWK);        // OH*ROWH*4 = 16448 B
    short*    wlist = (short*)(hist + OH * ROWH);      // OH*MAXREJ*2 = 7424 B

    int b = blockIdx.x >> 1;
    int obase = (blockIdx.x & 1) * OH;
    int tid = threadIdx.x;
    int w = tid >> 5, lane = tid & 31;

    // Reduce per-chunk partials -> den, num, v (for this o-half)
    if (tid < OH) {
        float s = 0.f;
#pragma unroll
        for (int c = 0; c < CHUNKS; c++)
            s += g_partd[(b * CHUNKS + c) * NO + obase + tid];
        sden[tid] = s;
    }
    for (int idx = tid; idx < OH * ROWH; idx += 512) hist[idx] = 0;
    __syncthreads();
    if (tid < OH * ND) {
        int ol = tid / ND, d = tid % ND;
        float s = 0.f;
#pragma unroll
        for (int c = 0; c < CHUNKS; c++)
            s += g_part[(size_t)(b * CHUNKS + c) * NO * ND + (obase + ol) * ND + d];
        snum[ol * ND + d] = s;
        sv[d * OH + ol] = s / sden[ol];
    }
    __syncthreads();

    // ---- Sweep: thread (ol = tid&15, isub = tid>>4) covers i = isub + 32*s.
    const float4* up = (const float4*)u + (size_t)b * NI * 128;
    int ol = tid & 15, isub = tid >> 4;
    const float4* base = up + (size_t)isub * 128 + (obase + ol) * 4;
#pragma unroll 2
    for (int s = 0; s < NI / 32; s++) {
        int i = isub + (s << 5);
        const float4* row = base + (size_t)(s << 5) * 128;
        float4 a0 = row[0], a1 = row[1], a2 = row[2], a3 = row[3];
        float va[16] = {a0.x, a0.y, a0.z, a0.w, a1.x, a1.y, a1.z, a1.w,
                        a2.x, a2.y, a2.z, a2.w, a3.x, a3.y, a3.z, a3.w};
        float dotv = 0.f;
#pragma unroll
        for (int d = 0; d < 16; d++) dotv += sv[d * OH + ol] * va[d];
        unsigned kk = mono_key(-dotv);
        keys[ol * ROWK + i] = kk;
        atomicAdd(&hist[ol * ROWH + (kk >> 24)], 1);
    }
    __syncthreads();

    // ---- Per-warp selection for o_local = w (16 warps; warp-private)
    unsigned* mk = keys + w * ROWK;
    int* oh = hist + w * ROWH;

    int k = KSUB;
    unsigned b1 = warp_pick(oh, lane, k);

#pragma unroll
    for (int t = 0; t < 8; t++) oh[lane * 8 + t] = 0;
    __syncwarp();
#pragma unroll 4
    for (int j = 0; j < NI / 32; j++) {
        unsigned kk = mk[j * 32 + lane];
        if ((kk >> 24) == b1) atomicAdd(&oh[(kk >> 16) & 255], 1);
    }
    __syncwarp();
    unsigned b2 = warp_pick(oh, lane, k);
    unsigned prefix16 = (b1 << 8) | b2;

#pragma unroll
    for (int t = 0; t < 8; t++) oh[lane * 8 + t] = 0;
    __syncwarp();
#pragma unroll 4
    for (int j = 0; j < NI / 32; j++) {
        unsigned kk = mk[j * 32 + lane];
        if ((kk >> 16) == prefix16) atomicAdd(&oh[(kk >> 8) & 255], 1);
    }
    __syncwarp();
    unsigned b3 = warp_pick(oh, lane, k);
    unsigned prefix24 = (prefix16 << 8) | b3;

#pragma unroll
    for (int t = 0; t < 8; t++) oh[lane * 8 + t] = 0;
    __syncwarp();
#pragma unroll 4
    for (int j = 0; j < NI / 32; j++) {
        unsigned kk = mk[j * 32 + lane];
        if ((kk >> 8) == prefix24) atomicAdd(&oh[kk & 255], 1);
    }
    __syncwarp();
    unsigned b4 = warp_pick(oh, lane, k);
    unsigned thrkey = (prefix24 << 8) | b4;   // exact k-th smallest key

    // ---- Rejected list (key > thrkey), atomic-free warp compaction
    short* wl = wlist + w * MAXREJ;
    int base2 = 0;
#pragma unroll 4
    for (int j = 0; j < NI / 32; j++) {
        bool rej = mk[j * 32 + lane] > thrkey;
        unsigned mba = __ballot_sync(0xffffffffu, rej);
        if (rej) wl[base2 + __popc(mba & ((1u << lane) - 1u))] =
            (short)(j * 32 + lane);
        base2 += __popc(mba);
    }
    int nr = base2;  // <= 230
    __syncwarp();

    // ---- Gather rejected capsules (L2-hot), 4 lanes/capsule, 2-deep batch
    int p = lane & 3, g = lane >> 2;
    const float4* gp = up + (obase + w) * 4 + p;
    float acc0 = 0.f, acc1 = 0.f, acc2 = 0.f, acc3 = 0.f, aden = 0.f;
    int nrp = (nr + 15) & ~15;
    for (int t = g; t < nrp; t += 16) {
        int t2 = t + 8;
        bool v1 = t < nr, v2 = t2 < nr;
        int i1 = v1 ? (int)wl[t] : 0;
        int i2 = v2 ? (int)wl[t2] : 0;
        float4 a = gp[(size_t)i1 * 128];
        float4 c = gp[(size_t)i2 * 128];
        if (!v1) { a.x = 0.f; a.y = 0.f; a.z = 0.f; a.w = 0.f; }
        if (!v2) { c.x = 0.f; c.y = 0.f; c.z = 0.f; c.w = 0.f; }
        float s1 = a.x * a.x + a.y * a.y + a.z * a.z + a.w * a.w;
        float s2 = c.x * c.x + c.y * c.y + c.z * c.z + c.w * c.w;
        s1 += __shfl_xor_sync(0xffffffffu, s1, 1);
        s2 += __shfl_xor_sync(0xffffffffu, s2, 1);
        s1 += __shfl_xor_sync(0xffffffffu, s1, 2);
        s2 += __shfl_xor_sync(0xffffffffu, s2, 2);
        float n1 = sqrtf(s1), n2 = sqrtf(s2);
        acc0 += a.x * n1 + c.x * n2;
        acc1 += a.y * n1 + c.y * n2;
        acc2 += a.z * n1 + c.z * n2;
        acc3 += a.w * n1 + c.w * n2;
        if (p == 0) aden += n1 + n2;
    }
    // reduce across the 8 quads (offsets 4,8,16 preserve p)
#pragma unroll
    for (int off = 4; off < 32; off <<= 1) {
        acc0 += __shfl_xor_sync(0xffffffffu, acc0, off);
        acc1 += __shfl_xor_sync(0xffffffffu, acc1, off);
        acc2 += __shfl_xor_sync(0xffffffffu, acc2, off);
        acc3 += __shfl_xor_sync(0xffffffffu, acc3, off);
    }
#pragma unroll
    for (int off = 1; off < 32; off <<= 1)
        aden += __shfl_xor_sync(0xffffffffu, aden, off);

    // lanes 0..3 (p = lane) hold elements 4p..4p+3 -> one float4 each
    if (lane < 4) {
        int bo = b * NO + obase + w;
        float4 nm = ((const float4*)snum)[w * 4 + lane];
        float den2 = sden[w] - aden;
        float4 r;
        r.x = (nm.x - acc0) / den2;
        r.y = (nm.y - acc1) / den2;
        r.z = (nm.z - acc2) / den2;
        r.w = (nm.w - acc3) / den2;
        ((float4*)out)[bo * 4 + lane] = r;
    }
}

#define SMEM_P2S ((OH * ND * 2 + OH) * 4 + OH * ROWK * 4 + OH * ROWH * 4 + OH * MAXREJ * 2)

extern "C" void kernel_launch(void* const* d_in, const int* in_sizes, int n_in,
                              void* d_out, int out_size) {
    const float* u = (const float*)d_in[0];
    float* out = (float*)d_out;

    cudaFuncSetAttribute(k_pass2sel,
                         cudaFuncAttributeMaxDynamicSharedMemorySize, SMEM_P2S);

    k_pass1<<<NB * CHUNKS, 256>>>(u);
    k_pass2sel<<<NB * 2, 512, SMEM_P2S>>>(u, out);
}

// round 17
// speedup vs baseline: 1.4494x; 1.4494x over previous
#include <cuda_runtime.h>
#include <math.h>

// Problem constants
#define NB 128
#define NI 1152
#define NO 32
#define ND 16
#define KSUB 922          // ceil(0.8 * 1152)
#define CHUNKS 9
#define IPB (NI / CHUNKS) // 128 i's per block (pass1)
#define IPW (IPB / 8)     // 16 i's per warp
#define MAXREJ 232        // >= NI - KSUB = 230
#define ROWK 1153         // key row stride in words (odd -> conflict-free)
#define ROWH 257          // hist row stride in words

// Scratch (no allocation allowed -> __device__ globals). Per-chunk partials:
// written race-free by pass1 (no atomics, no zeroing kernel needed).
__device__ float g_part [NB * CHUNKS * NO * ND];
__device__ float g_partd[NB * CHUNKS * NO];

// ---------------------------------------------------------------------------
// Pass 1: per-chunk partial sums of u*n and n  (no atomics, no pre-zero)
// ---------------------------------------------------------------------------
__global__ void __launch_bounds__(256) k_pass1(const float* __restrict__ u) {
    int b = blockIdx.x / CHUNKS;
    int chunk = blockIdx.x % CHUNKS;
    int w = threadIdx.x >> 5;
    int lane = threadIdx.x & 31;

    const float4* up = (const float4*)u + (size_t)b * NI * (NO * ND / 4);
    float acc[ND];
    float accden = 0.f;
#pragma unroll
    for (int d = 0; d < ND; d++) acc[d] = 0.f;

    int i0 = chunk * IPB + w * IPW;
#pragma unroll 2
    for (int ii = 0; ii < IPW; ii++) {
        const float4* row = up + (size_t)(i0 + ii) * (NO * ND / 4) + lane * (ND / 4);
        float4 a0 = row[0], a1 = row[1], a2 = row[2], a3 = row[3];
        float va[16] = {a0.x, a0.y, a0.z, a0.w, a1.x, a1.y, a1.z, a1.w,
                        a2.x, a2.y, a2.z, a2.w, a3.x, a3.y, a3.z, a3.w};
        float s = 0.f;
#pragma unroll
        for (int d = 0; d < 16; d++) s += va[d] * va[d];
        float n = sqrtf(s);
#pragma unroll
        for (int d = 0; d < 16; d++) acc[d] += va[d] * n;
        accden += n;
    }

    __shared__ float snum[8][NO * ND];
    __shared__ float sden[8][NO];
#pragma unroll
    for (int d = 0; d < ND; d++) snum[w][d * NO + lane] = acc[d];
    sden[w][lane] = accden;
    __syncthreads();

    float* gp = &g_part[(size_t)(b * CHUNKS + chunk) * NO * ND];
    for (int idx = threadIdx.x; idx < NO * ND; idx += 256) {
        int d = idx / NO, o = idx % NO;
        float s = 0.f;
#pragma unroll
        for (int ww = 0; ww < 8; ww++) s += snum[ww][idx];
        gp[o * ND + d] = s;
    }
    if (threadIdx.x < NO) {
        float s = 0.f;
#pragma unroll
        for (int ww = 0; ww < 8; ww++) s += sden[ww][threadIdx.x];
        g_partd[(b * CHUNKS + chunk) * NO + threadIdx.x] = s;
    }
}

__device__ __forceinline__ unsigned mono_key(float f) {
    unsigned x = __float_as_uint(f);
    return (x & 0x80000000u) ? ~x : (x | 0x80000000u);
}

// Warp pick: 256-bin hist row -> bucket containing rank k; updates k.
__device__ __forceinline__ unsigned warp_pick(const int* oh, int lane, int& k) {
    int h[8], seg = 0;
#pragma unroll
    for (int t = 0; t < 8; t++) { h[t] = oh[lane * 8 + t]; seg += h[t]; }
    int incl = seg;
#pragma unroll
    for (int off = 1; off < 32; off <<= 1) {
        int n_ = __shfl_up_sync(0xffffffffu, incl, off);
        if (lane >= off) incl += n_;
    }
    int excl = incl - seg;
    bool has = (excl < k) && (excl + seg >= k);
    unsigned mba = __ballot_sync(0xffffffffu, has);
    int src = __ffs(mba) - 1;
    int bsel = 0, kk2 = 0;
    if (lane == src) {
        int run = excl;
#pragma unroll
        for (int t = 0; t < 8; t++) {
            if (run + h[t] >= k) { bsel = lane * 8 + t; kk2 = k - run; break; }
            run += h[t];
        }
    }
    bsel = __shfl_sync(0xffffffffu, bsel, src);
    k = __shfl_sync(0xffffffffu, kk2, src);
    return (unsigned)bsel;
}

// ---------------------------------------------------------------------------
// Fused pass2 + select + fixup: ONE 1024-thread block per batch b (R14
// structure: warp-per-row sweep, full 32 o's). Front-end reduces per-chunk
// partials into smem (num/den/v) -- no k_zero, no atomics anywhere.
// ---------------------------------------------------------------------------
__global__ void __launch_bounds__(1024) k_pass2sel(const float* __restrict__ u,
                                                   float* __restrict__ out) {
    extern __shared__ char smem[];
    float*    sv    = (float*)smem;                    //  2048 B  sv[d*32+o]
    float*    snum  = sv + 512;                        //  2048 B  [o*ND+d]
    float*    sden  = snum + 512;                      //   128 B
    unsigned* keys  = (unsigned*)(sden + 32);          // 32*1153*4 = 147584 B
    int*      hist  = (int*)(keys + 32 * ROWK);        // 32*257*4  =  32896 B
    short*    wlist = (short*)(hist + 32 * ROWH);      // 32*232*2  =  14848 B

    int b = blockIdx.x;
    int tid = threadIdx.x;
    int w = tid >> 5, lane = tid & 31;

    // Reduce per-chunk partials -> den, num, v  (in smem)
    if (tid < NO) {
        float s = 0.f;
#pragma unroll
        for (int c = 0; c < CHUNKS; c++)
            s += g_partd[(b * CHUNKS + c) * NO + tid];
        sden[tid] = s;
    }
    for (int idx = tid; idx < 32 * ROWH; idx += 1024) hist[idx] = 0;
    __syncthreads();
    if (tid < NO * ND) {
        int o = tid / ND, d = tid % ND;
        float s = 0.f;
#pragma unroll
        for (int c = 0; c < CHUNKS; c++)
            s += g_part[(size_t)(b * CHUNKS + c) * NO * ND + tid];
        snum[tid] = s;
        sv[d * NO + o] = s / sden[o];
    }
    __syncthreads();

    // ---- Sweep: warp w handles i = w + 32*s. Lane = o. Keys + round-1 hist.
    const float4* up = (const float4*)u + (size_t)b * NI * 128;
#pragma unroll 2
    for (int s = 0; s < NI / 32; s++) {
        int i = w + (s << 5);
        const float4* row = up + (size_t)i * 128 + lane * 4;
        float4 a0 = row[0], a1 = row[1], a2 = row[2], a3 = row[3];
        float va[16] = {a0.x, a0.y, a0.z, a0.w, a1.x, a1.y, a1.z, a1.w,
                        a2.x, a2.y, a2.z, a2.w, a3.x, a3.y, a3.z, a3.w};
        float dotv = 0.f;
#pragma unroll
        for (int d = 0; d < 16; d++) dotv += sv[d * NO + lane] * va[d];
        unsigned kk = mono_key(-dotv);
        keys[lane * ROWK + i] = kk;
        atomicAdd(&hist[lane * ROWH + (kk >> 24)], 1);
    }
    __syncthreads();

    // ---- Per-warp selection for o = w (warp-private; __syncwarp only)
    unsigned* mk = keys + w * ROWK;
    int* oh = hist + w * ROWH;

    int k = KSUB;
    unsigned b1 = warp_pick(oh, lane, k);

    // round 2
#pragma unroll
    for (int t = 0; t < 8; t++) oh[lane * 8 + t] = 0;
    __syncwarp();
#pragma unroll 4
    for (int j = 0; j < NI / 32; j++) {
        unsigned kk = mk[j * 32 + lane];
        if ((kk >> 24) == b1) atomicAdd(&oh[(kk >> 16) & 255], 1);
    }
    __syncwarp();
    unsigned b2 = warp_pick(oh, lane, k);
    unsigned prefix16 = (b1 << 8) | b2;

    // round 3
#pragma unroll
    for (int t = 0; t < 8; t++) oh[lane * 8 + t] = 0;
    __syncwarp();
#pragma unroll 4
    for (int j = 0; j < NI / 32; j++) {
        unsigned kk = mk[j * 32 + lane];
        if ((kk >> 16) == prefix16) atomicAdd(&oh[(kk >> 8) & 255], 1);
    }
    __syncwarp();
    unsigned b3 = warp_pick(oh, lane, k);
    unsigned prefix24 = (prefix16 << 8) | b3;

    // round 4
#pragma unroll
    for (int t = 0; t < 8; t++) oh[lane * 8 + t] = 0;
    __syncwarp();
#pragma unroll 4
    for (int j = 0; j < NI / 32; j++) {
        unsigned kk = mk[j * 32 + lane];
        if ((kk >> 8) == prefix24) atomicAdd(&oh[kk & 255], 1);
    }
    __syncwarp();
    unsigned b4 = warp_pick(oh, lane, k);
    unsigned thrkey = (prefix24 << 8) | b4;   // exact k-th smallest key

    // ---- Rejected list (key > thrkey), atomic-free warp compaction
    short* wl = wlist + w * MAXREJ;
    int base = 0;
#pragma unroll 4
    for (int j = 0; j < NI / 32; j++) {
        bool rej = mk[j * 32 + lane] > thrkey;
        unsigned mba = __ballot_sync(0xffffffffu, rej);
        if (rej) wl[base + __popc(mba & ((1u << lane) - 1u))] =
            (short)(j * 32 + lane);
        base += __popc(mba);
    }
    int nr = base;  // <= 230
    __syncwarp();

    // ---- Gather rejected capsules (L2-hot), 4 lanes/capsule, 2-deep batch
    int p = lane & 3, g = lane >> 2;
    const float4* gp = up + w * 4 + p;
    float acc0 = 0.f, acc1 = 0.f, acc2 = 0.f, acc3 = 0.f, aden = 0.f;
    int nrp = (nr + 15) & ~15;
    for (int t = g; t < nrp; t += 16) {
        int t2 = t + 8;
        bool v1 = t < nr, v2 = t2 < nr;
        int i1 = v1 ? (int)wl[t] : 0;
        int i2 = v2 ? (int)wl[t2] : 0;
        float4 a = gp[(size_t)i1 * 128];
        float4 c = gp[(size_t)i2 * 128];
        if (!v1) { a.x = 0.f; a.y = 0.f; a.z = 0.f; a.w = 0.f; }
        if (!v2) { c.x = 0.f; c.y = 0.f; c.z = 0.f; c.w = 0.f; }
        float s1 = a.x * a.x + a.y * a.y + a.z * a.z + a.w * a.w;
        float s2 = c.x * c.x + c.y * c.y + c.z * c.z + c.w * c.w;
        s1 += __shfl_xor_sync(0xffffffffu, s1, 1);
        s2 += __shfl_xor_sync(0xffffffffu, s2, 1);
        s1 += __shfl_xor_sync(0xffffffffu, s1, 2);
        s2 += __shfl_xor_sync(0xffffffffu, s2, 2);
        float n1 = sqrtf(s1), n2 = sqrtf(s2);
        acc0 += a.x * n1 + c.x * n2;
        acc1 += a.y * n1 + c.y * n2;
        acc2 += a.z * n1 + c.z * n2;
        acc3 += a.w * n1 + c.w * n2;
        if (p == 0) aden += n1 + n2;
    }
    // reduce across the 8 quads (offsets 4,8,16 preserve p)
#pragma unroll
    for (int off = 4; off < 32; off <<= 1) {
        acc0 += __shfl_xor_sync(0xffffffffu, acc0, off);
        acc1 += __shfl_xor_sync(0xffffffffu, acc1, off);
        acc2 += __shfl_xor_sync(0xffffffffu, acc2, off);
        acc3 += __shfl_xor_sync(0xffffffffu, acc3, off);
    }
#pragma unroll
    for (int off = 1; off < 32; off <<= 1)
        aden += __shfl_xor_sync(0xffffffffu, aden, off);

    // lanes 0..3 (p = lane) hold elements 4p..4p+3 -> one float4 each
    if (lane < 4) {
        int bo = b * NO + w;
        float4 nm = ((const float4*)snum)[w * 4 + lane];
        float den2 = sden[w] - aden;
        float4 r;
        r.x = (nm.x - acc0) / den2;
        r.y = (nm.y - acc1) / den2;
        r.z = (nm.z - acc2) / den2;
        r.w = (nm.w - acc3) / den2;
        ((float4*)out)[bo * 4 + lane] = r;
    }
}

#define SMEM_P2S ((512 * 2 + 32) * 4 + 32 * ROWK * 4 + 32 * ROWH * 4 + 32 * MAXREJ * 2)

extern "C" void kernel_launch(void* const* d_in, const int* in_sizes, int n_in,
                              void* d_out, int out_size) {
    const float* u = (const float*)d_in[0];
    float* out = (float*)d_out;

    cudaFuncSetAttribute(k_pass2sel,
                         cudaFuncAttributeMaxDynamicSharedMemorySize, SMEM_P2S);

    k_pass1<<<NB * CHUNKS, 256>>>(u);
    k_pass2sel<<<NB, 1024, SMEM_P2S>>>(u, out);
}